// round 6
// baseline (speedup 1.0000x reference)
#include <cuda_runtime.h>
#include <cuda_fp16.h>
#include <math.h>

#define NN 50000
#define EE 800000
#define KKER 8

// ---------------- scratch (static device globals; no allocation) ------------
// layout: [N][c=0..31][k=0..7] of half2(chan c, chan c+32) = 51.2 MB
__device__ __half2 g_xt_h[(size_t)NN * 256];
__device__ float   g_root[(size_t)NN * 64];   // x @ W_root   12.8 MB
__device__ float   g_agg[(size_t)NN * 64];    // scatter target 12.8 MB
__device__ float   g_cnt[NN];
__device__ float   g_sums[128];               // [0:64) sum, [64:128) sumsq
__device__ int     g_is64;

// ---------------- K_detect: sniff edge_idx dtype (int64 vs int32) ----------
__global__ void k_detect(const int* __restrict__ eidx_raw) {
    __shared__ int sh[8];
    int acc = 0;
    for (int i = threadIdx.x; i < 2048; i += 256) acc |= eidx_raw[2 * i + 1];
    for (int o = 16; o > 0; o >>= 1) acc |= __shfl_xor_sync(0xffffffffu, acc, o);
    if ((threadIdx.x & 31) == 0) sh[threadIdx.x >> 5] = acc;
    __syncthreads();
    if (threadIdx.x == 0) {
        int a = 0;
        #pragma unroll
        for (int i = 0; i < 8; i++) a |= sh[i];
        g_is64 = (a == 0) ? 1 : 0;
    }
}

// ---------------- K_zero ----------------------------------------------------
__global__ void k_zero() {
    long i = (long)blockIdx.x * blockDim.x + threadIdx.x;
    const long nagg = (long)NN * 64;
    if (i < nagg) g_agg[i] = 0.0f;
    else if (i < nagg + NN) g_cnt[i - nagg] = 0.0f;
    else if (i < nagg + NN + 128) g_sums[i - nagg - NN] = 0.0f;
}

// ---------------- tensor-core GEMM helpers ----------------------------------
#define SMS 72   // smem stride in halves: 144B = 9*16B -> aligned + conflict-free

__device__ __forceinline__ unsigned smem_u32(const void* p) {
    return (unsigned)__cvta_generic_to_shared(p);
}
__device__ __forceinline__ void mma16816(float d[4], const unsigned a[4],
                                         const unsigned b[2]) {
    asm volatile(
        "mma.sync.aligned.m16n8k16.row.col.f32.f16.f16.f32 "
        "{%0,%1,%2,%3}, {%4,%5,%6,%7}, {%8,%9}, {%0,%1,%2,%3};\n"
        : "+f"(d[0]), "+f"(d[1]), "+f"(d[2]), "+f"(d[3])
        : "r"(a[0]), "r"(a[1]), "r"(a[2]), "r"(a[3]),
          "r"(b[0]), "r"(b[1]));
}
#define LDSM_X4(r0, r1, r2, r3, addr)                                        \
    asm volatile("ldmatrix.sync.aligned.m8n8.x4.shared.b16 {%0,%1,%2,%3}, [%4];" \
                 : "=r"(r0), "=r"(r1), "=r"(r2), "=r"(r3) : "r"(addr))
#define LDSM_X2(r0, r1, addr)                                                \
    asm volatile("ldmatrix.sync.aligned.m8n8.x2.shared.b16 {%0,%1}, [%2];"   \
                 : "=r"(r0), "=r"(r1) : "r"(addr))

// ---------------- K_gemm (tensor core): C[N,576] = x[N,64] @ [W_g | W_root] -
// One block = 128 rows; loop over nine 64-col blocks. ldmatrix fragment loads.
__global__ __launch_bounds__(256) void k_gemm_tc(
    const float* __restrict__ x, const float* __restrict__ Wg,
    const float* __restrict__ Wr)
{
    __shared__ __half As[128 * SMS];   // A row-major [row][k]
    __shared__ __half BsT[64 * SMS];   // B transposed [n][k]

    const int row0 = blockIdx.x * 128;
    const int tid  = threadIdx.x;
    const int warp = tid >> 5;
    const int lane = tid & 31;
    const int g    = lane >> 2;        // 0..7
    const int t2   = (lane & 3) * 2;   // 0,2,4,6
    const int wm = warp & 3;           // row sub-tile (32 rows)
    const int wn = warp >> 2;          // col sub-window (0..1)

    // ---- load A once: x[row0..row0+128][0..64] -> fp16 (float4 vectorized)
    #pragma unroll
    for (int i = tid; i < 128 * 16; i += 256) {
        int r = i >> 4, c4 = (i & 15) << 2;
        int gr = row0 + r;
        float4 v = make_float4(0.f, 0.f, 0.f, 0.f);
        if (gr < NN) v = *(const float4*)&x[(size_t)gr * 64 + c4];
        *(__half2*)&As[r * SMS + c4]     = __floats2half2_rn(v.x, v.y);
        *(__half2*)&As[r * SMS + c4 + 2] = __floats2half2_rn(v.z, v.w);
    }

    // ---- precompute ldmatrix lane addresses
    unsigned a_addr[2];
    #pragma unroll
    for (int ms = 0; ms < 2; ms++) {
        int r  = wm * 32 + ms * 16 + (lane & 15);
        int kc = (lane >> 4) << 3;
        a_addr[ms] = smem_u32(&As[r * SMS + kc]);
    }
    unsigned b_addr[4];
    #pragma unroll
    for (int ns = 0; ns < 4; ns++) {
        int r  = wn * 16 + (ns & 1) * 8 + (ns >> 1) * 32 + (lane & 7);
        int kc = ((lane >> 3) & 1) << 3;
        b_addr[ns] = smem_u32(&BsT[r * SMS + kc]);
    }

    for (int kblk = 0; kblk < 9; kblk++) {
        __syncthreads();
        // load B^T tile: BsT[n][k] = W[k][kblk*64 + n]  (float4 global reads)
        #pragma unroll
        for (int i = tid; i < 64 * 16; i += 256) {
            int k = i >> 4, c4 = (i & 15) << 2;
            float4 v = (kblk < 8)
                     ? *(const float4*)&Wg[k * 512 + kblk * 64 + c4]
                     : *(const float4*)&Wr[k * 64 + c4];
            BsT[(c4 + 0) * SMS + k] = __float2half_rn(v.x);
            BsT[(c4 + 1) * SMS + k] = __float2half_rn(v.y);
            BsT[(c4 + 2) * SMS + k] = __float2half_rn(v.z);
            BsT[(c4 + 3) * SMS + k] = __float2half_rn(v.w);
        }
        __syncthreads();

        float acc[2][4][4];
        #pragma unroll
        for (int ms = 0; ms < 2; ms++)
            #pragma unroll
            for (int ns = 0; ns < 4; ns++)
                #pragma unroll
                for (int j = 0; j < 4; j++) acc[ms][ns][j] = 0.0f;

        #pragma unroll
        for (int kk = 0; kk < 4; kk++) {
            const unsigned koff = kk * 32;   // 16 halves = 32 bytes
            unsigned a0[4], a1[4];
            LDSM_X4(a0[0], a0[1], a0[2], a0[3], a_addr[0] + koff);
            LDSM_X4(a1[0], a1[1], a1[2], a1[3], a_addr[1] + koff);
            unsigned b[4][2];
            #pragma unroll
            for (int ns = 0; ns < 4; ns++)
                LDSM_X2(b[ns][0], b[ns][1], b_addr[ns] + koff);
            #pragma unroll
            for (int ns = 0; ns < 4; ns++) {
                mma16816(acc[0][ns], a0, b[ns]);
                mma16816(acc[1][ns], a1, b[ns]);
            }
        }

        if (kblk < 8) {
            // xt layout: [row][c(0..31)][k]  (half2 pairs chan c / c+32)
            #pragma unroll
            for (int ms = 0; ms < 2; ms++)
                #pragma unroll
                for (int ns = 0; ns < 2; ns++)
                    #pragma unroll
                    for (int j = 0; j < 4; j++) {
                        int row = row0 + wm * 32 + ms * 16 + g + ((j >> 1) ? 8 : 0);
                        int c   = wn * 16 + ns * 8 + t2 + (j & 1);
                        if (row < NN) {
                            __half2 h = __floats2half2_rn(acc[ms][ns][j],
                                                          acc[ms][ns + 2][j]);
                            g_xt_h[(size_t)row * 256 + c * 8 + kblk] = h;
                        }
                    }
        } else {
            #pragma unroll
            for (int ms = 0; ms < 2; ms++)
                #pragma unroll
                for (int ns = 0; ns < 4; ns++)
                    #pragma unroll
                    for (int j = 0; j < 4; j++) {
                        int row = row0 + wm * 32 + ms * 16 + g + ((j >> 1) ? 8 : 0);
                        int c   = wn * 16 + (ns & 1) * 8 + (ns >> 1) * 32 + t2 + (j & 1);
                        if (row < NN) g_root[(size_t)row * 64 + c] = acc[ms][ns][j];
                    }
        }
    }
}

// ---------------- K_edge: gather / weight / scatter (2-edge ILP, wide loads) -
template <bool IS64>
__device__ __forceinline__ void edge_loop(
    const void* __restrict__ eidx,
    const float* __restrict__ eattr,
    float m0, float m1, float m2, float iv0, float iv1, float iv2,
    int lane, int warp, int nwarp)
{
    const long long* e64 = (const long long*)eidx;
    const int*       e32 = (const int*)eidx;

    for (int e = warp * 2; e < EE; e += nwarp * 2) {
        long long srcA, dstA, srcB, dstB;
        if (IS64) {
            srcA = e64[e];     dstA = e64[EE + e];
            srcB = e64[e + 1]; dstB = e64[EE + e + 1];
        } else {
            srcA = e32[e];     dstA = e32[EE + e];
            srcB = e32[e + 1]; dstB = e32[EE + e + 1];
        }

        // wide gathers: per lane two 16B loads (k=0..3, k=4..7), both edges
        const uint4* xrA = (const uint4*)(g_xt_h + (size_t)srcA * 256 + lane * 8);
        const uint4* xrB = (const uint4*)(g_xt_h + (size_t)srcB * 256 + lane * 8);
        uint4 pA0 = xrA[0], pA1 = xrA[1];
        uint4 pB0 = xrB[0], pB1 = xrB[1];

        float aA0 = eattr[(size_t)e * 3 + 0];
        float aA1 = eattr[(size_t)e * 3 + 1];
        float aA2 = eattr[(size_t)e * 3 + 2];
        float aB0 = eattr[(size_t)e * 3 + 3];
        float aB1 = eattr[(size_t)e * 3 + 4];
        float aB2 = eattr[(size_t)e * 3 + 5];

        float gkA = 0.0f, gkB = 0.0f;
        if (lane < KKER) {
            float d0 = aA0 - m0, d1 = aA1 - m1, d2 = aA2 - m2;
            gkA = __expf(d0 * d0 * iv0 + d1 * d1 * iv1 + d2 * d2 * iv2);
            d0 = aB0 - m0; d1 = aB1 - m1; d2 = aB2 - m2;
            gkB = __expf(d0 * d0 * iv0 + d1 * d1 * iv1 + d2 * d2 * iv2);
        }

        unsigned wA[8] = {pA0.x, pA0.y, pA0.z, pA0.w, pA1.x, pA1.y, pA1.z, pA1.w};
        unsigned wB[8] = {pB0.x, pB0.y, pB0.z, pB0.w, pB1.x, pB1.y, pB1.z, pB1.w};

        float accA0 = 0.0f, accA1 = 0.0f, accB0 = 0.0f, accB1 = 0.0f;
        #pragma unroll
        for (int k = 0; k < 8; k++) {
            float gA = __shfl_sync(0xffffffffu, gkA, k);
            float gB = __shfl_sync(0xffffffffu, gkB, k);
            float2 fA = __half22float2(*(__half2*)&wA[k]);
            float2 fB = __half22float2(*(__half2*)&wB[k]);
            accA0 = fmaf(gA, fA.x, accA0);
            accA1 = fmaf(gA, fA.y, accA1);
            accB0 = fmaf(gB, fB.x, accB0);
            accB1 = fmaf(gB, fB.y, accB1);
        }

        atomicAdd(&g_agg[(size_t)dstA * 64 + lane], accA0);
        atomicAdd(&g_agg[(size_t)dstA * 64 + 32 + lane], accA1);
        atomicAdd(&g_agg[(size_t)dstB * 64 + lane], accB0);
        atomicAdd(&g_agg[(size_t)dstB * 64 + 32 + lane], accB1);
        if (lane == 0) {
            atomicAdd(&g_cnt[dstA], 1.0f);
            atomicAdd(&g_cnt[dstB], 1.0f);
        }
    }
}

__global__ __launch_bounds__(256) void k_edge(
    const void* __restrict__ eidx,
    const float* __restrict__ eattr,
    const float* __restrict__ mu,
    const float* __restrict__ sigma)
{
    const int lane  = threadIdx.x & 31;
    const int warp  = ((int)blockIdx.x * (int)blockDim.x + (int)threadIdx.x) >> 5;
    const int nwarp = ((int)gridDim.x * (int)blockDim.x) >> 5;

    float m0 = 0.f, m1 = 0.f, m2 = 0.f, iv0 = 0.f, iv1 = 0.f, iv2 = 0.f;
    if (lane < KKER) {
        m0 = mu[lane * 3 + 0]; m1 = mu[lane * 3 + 1]; m2 = mu[lane * 3 + 2];
        float s0 = sigma[lane * 3 + 0], s1 = sigma[lane * 3 + 1], s2 = sigma[lane * 3 + 2];
        iv0 = -0.5f / (1e-15f + s0 * s0);
        iv1 = -0.5f / (1e-15f + s1 * s1);
        iv2 = -0.5f / (1e-15f + s2 * s2);
    }

    if (g_is64) edge_loop<true >(eidx, eattr, m0, m1, m2, iv0, iv1, iv2, lane, warp, nwarp);
    else        edge_loop<false>(eidx, eattr, m0, m1, m2, iv0, iv1, iv2, lane, warp, nwarp);
}

// ---------------- K_combine: pre-BN values + channel sums -------------------
__global__ __launch_bounds__(256) void k_combine(
    const float* __restrict__ bias, float* __restrict__ out)
{
    const int c = threadIdx.x & 63;
    const int w = threadIdx.x >> 6;   // 0..3
    const float b = bias[c];

    float s = 0.0f, ss = 0.0f;
    for (int n = blockIdx.x * 4 + w; n < NN; n += gridDim.x * 4) {
        float cnt = g_cnt[n];
        float inv = 1.0f / fmaxf(cnt, 1.0f);
        float v = g_agg[(size_t)n * 64 + c] * inv + g_root[(size_t)n * 64 + c] + b;
        out[(size_t)n * 64 + c] = v;
        s += v; ss += v * v;
    }

    __shared__ float shs[4][64];
    __shared__ float shq[4][64];
    shs[w][c] = s; shq[w][c] = ss;
    __syncthreads();
    if (threadIdx.x < 64) {
        float S  = shs[0][c] + shs[1][c] + shs[2][c] + shs[3][c];
        float SS = shq[0][c] + shq[1][c] + shq[2][c] + shq[3][c];
        atomicAdd(&g_sums[c], S);
        atomicAdd(&g_sums[64 + c], SS);
    }
}

// ---------------- K_norm: batchnorm + leaky relu -----------------------------
__global__ __launch_bounds__(256) void k_norm(
    const float* __restrict__ gamma, const float* __restrict__ beta,
    float* __restrict__ out)
{
    long i = (long)blockIdx.x * blockDim.x + threadIdx.x;
    if (i >= (long)NN * 64) return;
    int c = (int)(i & 63);
    const float invN = 1.0f / (float)NN;
    float mean = g_sums[c] * invN;
    float var  = g_sums[64 + c] * invN - mean * mean;
    float v = (out[i] - mean) * rsqrtf(var + 1e-5f) * gamma[c] + beta[c];
    out[i] = (v > 0.0f) ? v : 0.01f * v;
}

// ---------------- launcher ---------------------------------------------------
extern "C" void kernel_launch(void* const* d_in, const int* in_sizes, int n_in,
                              void* d_out, int out_size)
{
    const float* x      = (const float*)d_in[0];
    const void*  eidx   = d_in[1];
    const float* eattr  = (const float*)d_in[2];
    const float* Wg     = (const float*)d_in[3];
    const float* mu     = (const float*)d_in[4];
    const float* sigma  = (const float*)d_in[5];
    const float* Wr     = (const float*)d_in[6];
    const float* bias   = (const float*)d_in[7];
    const float* gamma  = (const float*)d_in[8];
    const float* beta   = (const float*)d_in[9];
    float* out = (float*)d_out;

    {
        long total = (long)NN * 64 + NN + 128;
        int blocks = (int)((total + 255) / 256);
        k_zero<<<blocks, 256>>>();
    }
    k_detect<<<1, 256>>>((const int*)eidx);
    k_gemm_tc<<<(NN + 127) / 128, 256>>>(x, Wg, Wr);
    k_edge<<<2368, 256>>>(eidx, eattr, mu, sigma);
    k_combine<<<512, 256>>>(bias, out);
    {
        int blocks = (int)(((long)NN * 64 + 255) / 256);
        k_norm<<<blocks, 256>>>(gamma, beta, out);
    }
}

// round 8
// speedup vs baseline: 1.2704x; 1.2704x over previous
#include <cuda_runtime.h>
#include <cuda_fp16.h>
#include <math.h>

#define NN 50000
#define EE 800000
#define KKER 8

// ---------------- scratch (static device globals; no allocation) ------------
// xt layout (R5): [row][kblk*32 + c], half2 pairs chan c / c+32  = 51.2 MB
__device__ __half2 g_xt_h[(size_t)NN * 256];
__device__ float   g_root[(size_t)NN * 64];   // x @ W_root   12.8 MB
__device__ float   g_agg[(size_t)NN * 64];    // scatter target 12.8 MB
__device__ float   g_cnt[NN];
__device__ float   g_sums[128];               // [0:64) sum, [64:128) sumsq
__device__ int     g_is64;
__device__ __half  g_Bh[9 * 4096];            // pre-swizzled B tiles (73.7 KB)

__device__ __forceinline__ unsigned h2_as_u32(__half2 h) {
    return *(unsigned*)&h;
}

// ---------------- K_detect ---------------------------------------------------
__global__ void k_detect(const int* __restrict__ eidx_raw) {
    __shared__ int sh[8];
    int acc = 0;
    for (int i = threadIdx.x; i < 2048; i += 256) acc |= eidx_raw[2 * i + 1];
    for (int o = 16; o > 0; o >>= 1) acc |= __shfl_xor_sync(0xffffffffu, acc, o);
    if ((threadIdx.x & 31) == 0) sh[threadIdx.x >> 5] = acc;
    __syncthreads();
    if (threadIdx.x == 0) {
        int a = 0;
        #pragma unroll
        for (int i = 0; i < 8; i++) a |= sh[i];
        g_is64 = (a == 0) ? 1 : 0;
    }
}

// ---------------- K_zero ------------------------------------------------------
__global__ void k_zero() {
    long i = (long)blockIdx.x * blockDim.x + threadIdx.x;
    const long nagg = (long)NN * 64;
    if (i < nagg) g_agg[i] = 0.0f;
    else if (i < nagg + NN) g_cnt[i - nagg] = 0.0f;
    else if (i < nagg + NN + 128) g_sums[i - nagg - NN] = 0.0f;
}

// ---------------- K_prepB: B^T tiles -> fp16, XOR-swizzled ------------------
// Per kblk, logical (n,k) n,k in [0,64): half index = n*64 + ((k>>3)^(n&7))*8 + (k&7)
__global__ void k_prepB(const float* __restrict__ Wg, const float* __restrict__ Wr) {
    int idx = blockIdx.x * 256 + threadIdx.x;
    if (idx >= 9 * 4096) return;
    int kblk = idx >> 12;
    int n = (idx >> 6) & 63;
    int k = idx & 63;
    float v = (kblk < 8) ? Wg[k * 512 + kblk * 64 + n] : Wr[k * 64 + n];
    int swz = n * 64 + (((k >> 3) ^ (n & 7)) << 3) + (k & 7);
    g_Bh[kblk * 4096 + swz] = __float2half_rn(v);
}

// ---------------- tensor-core GEMM ------------------------------------------
__device__ __forceinline__ unsigned smem_u32(const void* p) {
    return (unsigned)__cvta_generic_to_shared(p);
}
__device__ __forceinline__ void mma16816(float d[4], const unsigned a[4],
                                         unsigned b0, unsigned b1) {
    asm volatile(
        "mma.sync.aligned.m16n8k16.row.col.f32.f16.f16.f32 "
        "{%0,%1,%2,%3}, {%4,%5,%6,%7}, {%8,%9}, {%0,%1,%2,%3};\n"
        : "+f"(d[0]), "+f"(d[1]), "+f"(d[2]), "+f"(d[3])
        : "r"(a[0]), "r"(a[1]), "r"(a[2]), "r"(a[3]), "r"(b0), "r"(b1));
}
#define LDSM_X4(r0, r1, r2, r3, addr)                                        \
    asm volatile("ldmatrix.sync.aligned.m8n8.x4.shared.b16 {%0,%1,%2,%3}, [%4];" \
                 : "=r"(r0), "=r"(r1), "=r"(r2), "=r"(r3) : "r"(addr))

// One block = 128 rows; A frags hoisted; 9 kblk with linear 8KB B copies.
__global__ __launch_bounds__(256) void k_gemm_tc(const float* __restrict__ x)
{
    __shared__ __half As[128 * 64];  // 128B rows, XOR swizzle
    __shared__ __half Bs[64 * 64];   // one kblk tile, pre-swizzled image

    const int row0 = blockIdx.x * 128;
    const int tid  = threadIdx.x;
    const int warp = tid >> 5;
    const int lane = tid & 31;
    const int g    = lane >> 2;
    const int t2   = (lane & 3) * 2;
    const int wm = warp & 3;
    const int wn = warp >> 2;

    // ---- fill A (XOR swizzled): thread handles 4 chunks of 8 halves
    #pragma unroll
    for (int j = 0; j < 4; j++) {
        int cid = tid + j * 256;          // 0..1023
        int r = cid >> 3, kc = cid & 7;
        int gr = row0 + r;
        float4 v0 = make_float4(0.f, 0.f, 0.f, 0.f);
        float4 v1 = make_float4(0.f, 0.f, 0.f, 0.f);
        if (gr < NN) {
            v0 = *(const float4*)&x[(size_t)gr * 64 + kc * 8];
            v1 = *(const float4*)&x[(size_t)gr * 64 + kc * 8 + 4];
        }
        uint4 u;
        u.x = h2_as_u32(__floats2half2_rn(v0.x, v0.y));
        u.y = h2_as_u32(__floats2half2_rn(v0.z, v0.w));
        u.z = h2_as_u32(__floats2half2_rn(v1.x, v1.y));
        u.w = h2_as_u32(__floats2half2_rn(v1.z, v1.w));
        *(uint4*)&As[r * 64 + ((kc ^ (r & 7)) << 3)] = u;
    }
    __syncthreads();

    // ---- hoist A fragments: a[ms][kk][4]
    unsigned a[2][4][4];
    #pragma unroll
    for (int ms = 0; ms < 2; ms++)
        #pragma unroll
        for (int kk = 0; kk < 4; kk++) {
            int r  = wm * 32 + ms * 16 + (lane & 15);
            int ch = kk * 2 + (lane >> 4);
            unsigned ad = smem_u32(&As[r * 64 + ((ch ^ (r & 7)) << 3)]);
            LDSM_X4(a[ms][kk][0], a[ms][kk][1], a[ms][kk][2], a[ms][kk][3], ad);
        }

    const uint4* bsrc = (const uint4*)g_Bh;
    uint4* bdst = (uint4*)Bs;

    for (int kblk = 0; kblk < 9; kblk++) {
        __syncthreads();
        // linear copy of pre-swizzled 8KB tile (conflict-free)
        bdst[tid]       = bsrc[kblk * 512 + tid];
        bdst[tid + 256] = bsrc[kblk * 512 + tid + 256];
        __syncthreads();

        float acc[2][4][4];
        #pragma unroll
        for (int ms = 0; ms < 2; ms++)
            #pragma unroll
            for (int ns = 0; ns < 4; ns++)
                #pragma unroll
                for (int j = 0; j < 4; j++) acc[ms][ns][j] = 0.0f;

        #pragma unroll
        for (int kk = 0; kk < 4; kk++) {
            int ch = kk * 2 + (lane >> 4);
            int n0 = wn * 16 + (lane & 15);
            int n1 = n0 + 32;
            unsigned b0[4], b1[4];
            LDSM_X4(b0[0], b0[1], b0[2], b0[3],
                    smem_u32(&Bs[n0 * 64 + ((ch ^ (n0 & 7)) << 3)]));
            LDSM_X4(b1[0], b1[1], b1[2], b1[3],
                    smem_u32(&Bs[n1 * 64 + ((ch ^ (n1 & 7)) << 3)]));
            #pragma unroll
            for (int ms = 0; ms < 2; ms++) {
                mma16816(acc[ms][0], a[ms][kk], b0[0], b0[2]);
                mma16816(acc[ms][1], a[ms][kk], b0[1], b0[3]);
                mma16816(acc[ms][2], a[ms][kk], b1[0], b1[2]);
                mma16816(acc[ms][3], a[ms][kk], b1[1], b1[3]);
            }
        }

        if (kblk < 8) {
            #pragma unroll
            for (int ms = 0; ms < 2; ms++)
                #pragma unroll
                for (int ns = 0; ns < 2; ns++)
                    #pragma unroll
                    for (int j = 0; j < 4; j++) {
                        int row = row0 + wm * 32 + ms * 16 + g + ((j >> 1) ? 8 : 0);
                        int c   = wn * 16 + ns * 8 + t2 + (j & 1);
                        if (row < NN) {
                            __half2 h = __floats2half2_rn(acc[ms][ns][j],
                                                          acc[ms][ns + 2][j]);
                            g_xt_h[(size_t)row * 256 + kblk * 32 + c] = h;
                        }
                    }
        } else {
            #pragma unroll
            for (int ms = 0; ms < 2; ms++)
                #pragma unroll
                for (int ns = 0; ns < 4; ns++)
                    #pragma unroll
                    for (int j = 0; j < 4; j++) {
                        int row = row0 + wm * 32 + ms * 16 + g + ((j >> 1) ? 8 : 0);
                        int c   = wn * 16 + (ns & 1) * 8 + (ns >> 1) * 32 + t2 + (j & 1);
                        if (row < NN) g_root[(size_t)row * 64 + c] = acc[ms][ns][j];
                    }
        }
    }
}

// ---------------- K_edge (exact R5: 2-edge ILP, [row][kblk][c] gathers) ------
template <bool IS64>
__device__ __forceinline__ void edge_loop(
    const void* __restrict__ eidx,
    const float* __restrict__ eattr,
    float m0, float m1, float m2, float iv0, float iv1, float iv2,
    int lane, int warp, int nwarp)
{
    const long long* e64 = (const long long*)eidx;
    const int*       e32 = (const int*)eidx;

    for (int e = warp * 2; e < EE; e += nwarp * 2) {
        long long srcA, dstA, srcB, dstB;
        if (IS64) {
            srcA = e64[e];     dstA = e64[EE + e];
            srcB = e64[e + 1]; dstB = e64[EE + e + 1];
        } else {
            srcA = e32[e];     dstA = e32[EE + e];
            srcB = e32[e + 1]; dstB = e32[EE + e + 1];
        }

        float aA0 = eattr[(size_t)e * 3 + 0];
        float aA1 = eattr[(size_t)e * 3 + 1];
        float aA2 = eattr[(size_t)e * 3 + 2];
        float aB0 = eattr[(size_t)e * 3 + 3];
        float aB1 = eattr[(size_t)e * 3 + 4];
        float aB2 = eattr[(size_t)e * 3 + 5];

        const __half2* xrA = g_xt_h + (size_t)srcA * 256;
        const __half2* xrB = g_xt_h + (size_t)srcB * 256;
        __half2 vA[8], vB[8];
        #pragma unroll
        for (int k = 0; k < 8; k++) vA[k] = xrA[k * 32 + lane];
        #pragma unroll
        for (int k = 0; k < 8; k++) vB[k] = xrB[k * 32 + lane];

        float gkA = 0.0f, gkB = 0.0f;
        if (lane < KKER) {
            float d0 = aA0 - m0, d1 = aA1 - m1, d2 = aA2 - m2;
            gkA = __expf(d0 * d0 * iv0 + d1 * d1 * iv1 + d2 * d2 * iv2);
            d0 = aB0 - m0; d1 = aB1 - m1; d2 = aB2 - m2;
            gkB = __expf(d0 * d0 * iv0 + d1 * d1 * iv1 + d2 * d2 * iv2);
        }

        float accA0 = 0.0f, accA1 = 0.0f, accB0 = 0.0f, accB1 = 0.0f;
        #pragma unroll
        for (int k = 0; k < 8; k++) {
            float gA = __shfl_sync(0xffffffffu, gkA, k);
            float gB = __shfl_sync(0xffffffffu, gkB, k);
            float2 fA = __half22float2(vA[k]);
            float2 fB = __half22float2(vB[k]);
            accA0 = fmaf(gA, fA.x, accA0);
            accA1 = fmaf(gA, fA.y, accA1);
            accB0 = fmaf(gB, fB.x, accB0);
            accB1 = fmaf(gB, fB.y, accB1);
        }

        atomicAdd(&g_agg[(size_t)dstA * 64 + lane], accA0);
        atomicAdd(&g_agg[(size_t)dstA * 64 + 32 + lane], accA1);
        atomicAdd(&g_agg[(size_t)dstB * 64 + lane], accB0);
        atomicAdd(&g_agg[(size_t)dstB * 64 + 32 + lane], accB1);
        if (lane == 0) {
            atomicAdd(&g_cnt[dstA], 1.0f);
            atomicAdd(&g_cnt[dstB], 1.0f);
        }
    }
}

__global__ __launch_bounds__(256) void k_edge(
    const void* __restrict__ eidx,
    const float* __restrict__ eattr,
    const float* __restrict__ mu,
    const float* __restrict__ sigma)
{
    const int lane  = threadIdx.x & 31;
    const int warp  = ((int)blockIdx.x * (int)blockDim.x + (int)threadIdx.x) >> 5;
    const int nwarp = ((int)gridDim.x * (int)blockDim.x) >> 5;

    float m0 = 0.f, m1 = 0.f, m2 = 0.f, iv0 = 0.f, iv1 = 0.f, iv2 = 0.f;
    if (lane < KKER) {
        m0 = mu[lane * 3 + 0]; m1 = mu[lane * 3 + 1]; m2 = mu[lane * 3 + 2];
        float s0 = sigma[lane * 3 + 0], s1 = sigma[lane * 3 + 1], s2 = sigma[lane * 3 + 2];
        iv0 = -0.5f / (1e-15f + s0 * s0);
        iv1 = -0.5f / (1e-15f + s1 * s1);
        iv2 = -0.5f / (1e-15f + s2 * s2);
    }

    if (g_is64) edge_loop<true >(eidx, eattr, m0, m1, m2, iv0, iv1, iv2, lane, warp, nwarp);
    else        edge_loop<false>(eidx, eattr, m0, m1, m2, iv0, iv1, iv2, lane, warp, nwarp);
}

// ---------------- K_combine ---------------------------------------------------
__global__ __launch_bounds__(256) void k_combine(
    const float* __restrict__ bias, float* __restrict__ out)
{
    const int c = threadIdx.x & 63;
    const int w = threadIdx.x >> 6;
    const float b = bias[c];

    float s = 0.0f, ss = 0.0f;
    for (int n = blockIdx.x * 4 + w; n < NN; n += gridDim.x * 4) {
        float cnt = g_cnt[n];
        float inv = 1.0f / fmaxf(cnt, 1.0f);
        float v = g_agg[(size_t)n * 64 + c] * inv + g_root[(size_t)n * 64 + c] + b;
        out[(size_t)n * 64 + c] = v;
        s += v; ss += v * v;
    }

    __shared__ float shs[4][64];
    __shared__ float shq[4][64];
    shs[w][c] = s; shq[w][c] = ss;
    __syncthreads();
    if (threadIdx.x < 64) {
        float S  = shs[0][c] + shs[1][c] + shs[2][c] + shs[3][c];
        float SS = shq[0][c] + shq[1][c] + shq[2][c] + shq[3][c];
        atomicAdd(&g_sums[c], S);
        atomicAdd(&g_sums[64 + c], SS);
    }
}

// ---------------- K_norm -------------------------------------------------------
__global__ __launch_bounds__(256) void k_norm(
    const float* __restrict__ gamma, const float* __restrict__ beta,
    float* __restrict__ out)
{
    long i = (long)blockIdx.x * blockDim.x + threadIdx.x;
    if (i >= (long)NN * 64) return;
    int c = (int)(i & 63);
    const float invN = 1.0f / (float)NN;
    float mean = g_sums[c] * invN;
    float var  = g_sums[64 + c] * invN - mean * mean;
    float v = (out[i] - mean) * rsqrtf(var + 1e-5f) * gamma[c] + beta[c];
    out[i] = (v > 0.0f) ? v : 0.01f * v;
}

// ---------------- launcher ------------------------------------------------------
extern "C" void kernel_launch(void* const* d_in, const int* in_sizes, int n_in,
                              void* d_out, int out_size)
{
    const float* x      = (const float*)d_in[0];
    const void*  eidx   = d_in[1];
    const float* eattr  = (const float*)d_in[2];
    const float* Wg     = (const float*)d_in[3];
    const float* mu     = (const float*)d_in[4];
    const float* sigma  = (const float*)d_in[5];
    const float* Wr     = (const float*)d_in[6];
    const float* bias   = (const float*)d_in[7];
    const float* gamma  = (const float*)d_in[8];
    const float* beta   = (const float*)d_in[9];
    float* out = (float*)d_out;

    {
        long total = (long)NN * 64 + NN + 128;
        int blocks = (int)((total + 255) / 256);
        k_zero<<<blocks, 256>>>();
    }
    k_detect<<<1, 256>>>((const int*)eidx);
    k_prepB<<<144, 256>>>(Wg, Wr);
    k_gemm_tc<<<(NN + 127) / 128, 256>>>(x);
    k_edge<<<2368, 256>>>(eidx, eattr, mu, sigma);
    k_combine<<<512, 256>>>(bias, out);
    {
        int blocks = (int)(((long)NN * 64 + 255) / 256);
        k_norm<<<blocks, 256>>>(gamma, beta, out);
    }
}